// round 7
// baseline (speedup 1.0000x reference)
#include <cuda_runtime.h>

// newPad2d: replicate (edge) pad, width 2 on H and W.
// in:  (32, 256, 56, 56) fp32 = 98 MB  -> 8192 planes of 56x56
// out: (32, 256, 60, 60) fp32 = 112 MB -> 8192 planes of 60x60
//
// PERSISTENT grid-stride version: grid = 148*8 = 1184 CTAs (one wave),
// each looping over 1024-vec chunks. Eliminates the ~12 wave transitions
// of the 7200-block grid (each ~2360 cyc of ramp-down/up with DRAM idle).
// Body = R4/R6: every output float4 starts at w0=4k, so its source window
// [w0-2,w0+2) is covered by TWO aligned LDG.64 + 2 selects. ILP=4.
// Stores use st.global.cs (streaming).
// Total chunks = 7,372,800/1024 = 7200 (all full; no per-element bounds).

#define IN_H   56
#define IN_W   56
#define PAD    2
#define PLANE_IN      (IN_H * IN_W)          // 3136
#define VEC_PER_ROW   15                     // 60/4
#define VEC_PER_PLANE (60 * VEC_PER_ROW)     // 900
#define ILP 4
#define THREADS 256
#define CHUNK (THREADS * ILP)                // 1024
#define TOTAL_CHUNKS 7200
#define GRID 1184                            // 148 SMs * 8 CTAs

__device__ __forceinline__ void stg_stream(float4* p, float4 v) {
    asm volatile("st.global.cs.v4.f32 [%0], {%1,%2,%3,%4};"
                 :: "l"(p), "f"(v.x), "f"(v.y), "f"(v.z), "f"(v.w)
                 : "memory");
}

__global__ __launch_bounds__(THREADS)
void pad2d_edge_persist(const float* __restrict__ x,
                        float4* __restrict__ out)
{
    for (int c = blockIdx.x; c < TOTAL_CHUNKS; c += GRID) {
        const int base = c * CHUNK + threadIdx.x;

        float2 a[ILP], b[ILP];
        int    w0[ILP];

#pragma unroll
        for (int k = 0; k < ILP; k++) {
            int idx   = base + k * THREADS;
            int plane = idx / VEC_PER_PLANE;
            int rem   = idx - plane * VEC_PER_PLANE;
            int h     = rem / VEC_PER_ROW;
            int w     = (rem - h * VEC_PER_ROW) * 4;
            w0[k]     = w;
            int hin   = min(max(h - PAD, 0), IN_H - 1);
            int off   = plane * PLANE_IN + hin * IN_W;  // max ~25.7M, 32-bit ok

            // both addresses 8-byte aligned
            a[k] = __ldg((const float2*)(x + off + max(w - 2, 0)));
            b[k] = __ldg((const float2*)(x + off + min(w, IN_W - 2)));
        }

#pragma unroll
        for (int k = 0; k < ILP; k++) {
            int w = w0[k];
            float4 v;
            v.x = a[k].x;
            v.y = (w == 0)    ? a[k].x : a[k].y;  // left edge replicates col 0
            v.z = (w == IN_W) ? b[k].y : b[k].x;  // right edge replicates col 55
            v.w = b[k].y;
            stg_stream(out + base + k * THREADS, v);
        }
    }
}

extern "C" void kernel_launch(void* const* d_in, const int* in_sizes, int n_in,
                              void* d_out, int out_size)
{
    const float* x = (const float*)d_in[0];
    float4* out = (float4*)d_out;

    pad2d_edge_persist<<<GRID, THREADS>>>(x, out);
}

// round 8
// speedup vs baseline: 1.1387x; 1.1387x over previous
#include <cuda_runtime.h>

// newPad2d: replicate (edge) pad, width 2 on H and W.
// in:  (32, 256, 56, 56) fp32 -> 8192 planes of 56x56
// out: (32, 256, 60, 60) fp32 -> 8192 planes of 60x60
//
// R4/R6 body + 256-bit stores (sm_103 supports st.global.v4.b64 = 32B).
// Output plane = 3600 floats (div by 8), so vec8s never cross planes, and
// each vec8 is exactly two consecutive vec4s; each vec4 is row-local with
// w0 % 4 == 0 -> its source window [w0-2, w0+2) is two aligned LDG.64.
// Per thread: ILP=2 vec8 (same bytes as R4's ILP=4 vec4) -> 8 LDG.64 +
// 2 STG.256, regs ~32, occupancy ~80%.
// nvec8 = 3,686,400 = 7200 * 512 exactly -> no tail.

#define IN_H   56
#define IN_W   56
#define PAD    2
#define PLANE_IN      (IN_H * IN_W)          // 3136
#define VEC_PER_ROW   15                     // vec4 per output row
#define VEC_PER_PLANE (60 * VEC_PER_ROW)     // 900 vec4 per plane
#define ILP 2                                // vec8 per thread
#define THREADS 256
#define CHUNK (THREADS * ILP)                // 512 vec8 per block

typedef unsigned long long ull;

__device__ __forceinline__ ull pack2(float lo, float hi) {
    return ((ull)__float_as_uint(hi) << 32) | (ull)__float_as_uint(lo);
}

__device__ __forceinline__ void stg256_stream(void* p, float4 lo, float4 hi) {
    ull u0 = pack2(lo.x, lo.y);
    ull u1 = pack2(lo.z, lo.w);
    ull u2 = pack2(hi.x, hi.y);
    ull u3 = pack2(hi.z, hi.w);
    asm volatile("st.global.cs.v4.b64 [%0], {%1,%2,%3,%4};"
                 :: "l"(p), "l"(u0), "l"(u1), "l"(u2), "l"(u3)
                 : "memory");
}

// Compute one output vec4 (R4 primitive). v4idx = global vec4 index.
__device__ __forceinline__ float4 make_vec4(const float* __restrict__ x, int v4idx)
{
    int plane = v4idx / VEC_PER_PLANE;
    int rem   = v4idx - plane * VEC_PER_PLANE;
    int h     = rem / VEC_PER_ROW;
    int w     = (rem - h * VEC_PER_ROW) * 4;
    int hin   = min(max(h - PAD, 0), IN_H - 1);
    int off   = plane * PLANE_IN + hin * IN_W;   // max ~25.7M, fits 32-bit

    // both addresses 8-byte aligned
    float2 a = __ldg((const float2*)(x + off + max(w - 2, 0)));
    float2 b = __ldg((const float2*)(x + off + min(w, IN_W - 2)));

    float4 v;
    v.x = a.x;
    v.y = (w == 0)    ? a.x : a.y;   // left edge replicates col 0
    v.z = (w == IN_W) ? b.y : b.x;   // right edge replicates col 55
    v.w = b.y;
    return v;
}

__global__ __launch_bounds__(THREADS)
void pad2d_edge_v8(const float* __restrict__ x,
                   float* __restrict__ out)
{
    const int base8 = blockIdx.x * CHUNK + threadIdx.x;   // vec8 index

    float4 lo[ILP], hi[ILP];
#pragma unroll
    for (int k = 0; k < ILP; k++) {
        int v8 = base8 + k * THREADS;
        lo[k] = make_vec4(x, 2 * v8);
        hi[k] = make_vec4(x, 2 * v8 + 1);
    }

#pragma unroll
    for (int k = 0; k < ILP; k++) {
        int v8 = base8 + k * THREADS;
        stg256_stream(out + (size_t)v8 * 8, lo[k], hi[k]);
    }
}

extern "C" void kernel_launch(void* const* d_in, const int* in_sizes, int n_in,
                              void* d_out, int out_size)
{
    const float* x = (const float*)d_in[0];
    float* out = (float*)d_out;

    int nvec8 = out_size / 8;        // 3,686,400
    int blocks = nvec8 / CHUNK;      // 7200 exactly
    pad2d_edge_v8<<<blocks, THREADS>>>(x, out);
}